// round 11
// baseline (speedup 1.0000x reference)
#include <cuda_runtime.h>
#include <cuda_fp16.h>
#include <math.h>
#include <stdint.h>

// Problem constants
#define HDIM   2880
#define NHEADS 64
#define NKV    8
#define DHEAD  64
#define GRP    8          // NHEADS / NKV
#define WIN    128
#define QKVW   5120       // (NHEADS + 2*NKV) * DHEAD
#define AOW    4096       // NHEADS * DHEAD
#define NMAX   1024

// Scratch (device globals: allocation-free)
__device__ float g_qkv[NMAX * QKVW];   // 20 MB
__device__ int   g_positions[NMAX];

__device__ __align__(16) __half g_ah[NMAX * HDIM];    // fp16 hidden states
__device__ __align__(16) __half g_ath[NMAX * AOW];    // fp16 attn output
__device__ __align__(16) __half g_wq[HDIM * QKVW];    // fp16 Wqkv
__device__ __align__(16) __half g_wo[AOW * HDIM];     // fp16 Wo

// ---------------------------------------------------------------------------
// positions normalizer (int32 vs int64 robust; positions are arange here)
// ---------------------------------------------------------------------------
__global__ void norm_pos_kernel(const void* __restrict__ pos_raw, int n)
{
    const long long* p64 = (const long long*)pos_raw;
    const int*       p32 = (const int*)pos_raw;
    __shared__ int is64;
    if (threadIdx.x == 0) {
        long long v0 = p64[0];
        long long v1 = (n > 1) ? p64[1] : 1;
        is64 = (v0 == 0 && v1 == 1) ? 1 : 0;
    }
    __syncthreads();
    for (int i = threadIdx.x; i < n; i += blockDim.x)
        g_positions[i] = is64 ? (int)p64[i] : p32[i];
}

// ---------------------------------------------------------------------------
// fused fp32 -> fp16 conversion of hs, Wqkv, Wo (one launch)
// ---------------------------------------------------------------------------
__device__ __forceinline__ void cvt4(const float* __restrict__ s,
                                     __half* __restrict__ d, int i)
{
    float4 v = ((const float4*)s)[i];
    __half2 p0 = __halves2half2(__float2half(v.x), __float2half(v.y));
    __half2 p1 = __halves2half2(__float2half(v.z), __float2half(v.w));
    uint2 o;
    o.x = *(uint32_t*)&p0; o.y = *(uint32_t*)&p1;
    ((uint2*)d)[i] = o;
}

__global__ void cvt_all_kernel(const float* __restrict__ hs,
                               const float* __restrict__ wqkv,
                               const float* __restrict__ wo,
                               __half* __restrict__ ah,
                               __half* __restrict__ wq,
                               __half* __restrict__ wo16,
                               int n4_hs, int n4_wq, int n4_wo)
{
    int i = blockIdx.x * blockDim.x + threadIdx.x;
    if (i < n4_hs) { cvt4(hs, ah, i); return; }
    i -= n4_hs;
    if (i < n4_wq) { cvt4(wqkv, wq, i); return; }
    i -= n4_wq;
    if (i < n4_wo) { cvt4(wo, wo16, i); }
}

// ---------------------------------------------------------------------------
// MMA helpers
// ---------------------------------------------------------------------------
__device__ __forceinline__ uint32_t smem_u32(const void* p) {
    return (uint32_t)__cvta_generic_to_shared(p);
}
__device__ __forceinline__ void ldsm_x4(uint32_t* r, uint32_t addr) {
    asm volatile("ldmatrix.sync.aligned.m8n8.x4.shared.b16 {%0,%1,%2,%3}, [%4];"
        : "=r"(r[0]), "=r"(r[1]), "=r"(r[2]), "=r"(r[3]) : "r"(addr));
}
__device__ __forceinline__ void ldsm_x4_t(uint32_t* r, uint32_t addr) {
    asm volatile("ldmatrix.sync.aligned.m8n8.x4.trans.shared.b16 {%0,%1,%2,%3}, [%4];"
        : "=r"(r[0]), "=r"(r[1]), "=r"(r[2]), "=r"(r[3]) : "r"(addr));
}
__device__ __forceinline__ void mma_fp16(float* d, const uint32_t* a, const uint32_t* b) {
    asm volatile(
        "mma.sync.aligned.m16n8k16.row.col.f32.f16.f16.f32 "
        "{%0,%1,%2,%3}, {%4,%5,%6,%7}, {%8,%9}, {%0,%1,%2,%3};"
        : "+f"(d[0]), "+f"(d[1]), "+f"(d[2]), "+f"(d[3])
        : "r"(a[0]), "r"(a[1]), "r"(a[2]), "r"(a[3]), "r"(b[0]), "r"(b[1]));
}
__device__ __forceinline__ void cp16(uint32_t dst, const void* src) {
    asm volatile("cp.async.cg.shared.global [%0], [%1], 16;"
        :: "r"(dst), "l"(src));
}

// ---------------------------------------------------------------------------
// 1-pass fp16 GEMM, BK=64 stages, 3-stage cp.async pipeline with a SINGLE
// __syncthreads per k-iteration (CUTLASS ordering), 2 CTAs/SM.
// C[M,N] = A @ B, fp32 accum.  A [M][K], B [K][N] row-major, both fp16.
// Block tile 128 x TN_ x 64; warps 2 x (TN_/32), warp tile 64x32.
// Requires M%128==0, N%TN_==0, K%64==0.
// ---------------------------------------------------------------------------
extern __shared__ char dsm[];

#define BK 64
#define SKA_H 72   // A smem row stride in halves (144B): conflict-free ldsm

template<int TN_>
__global__ __launch_bounds__(TN_ * 2, 2) void gemm1p_kernel(
    const __half* __restrict__ A, const __half* __restrict__ B,
    float* __restrict__ C, int M, int N, int K)
{
    constexpr int NT   = TN_ * 2;
    constexpr int SKB_ = TN_ + 8;                       // halves
    constexpr uint32_t OFF_B = 128u * SKA_H * 2u;       // 18432
    constexpr uint32_t STG   = OFF_B + (uint32_t)BK * SKB_ * 2u;
    constexpr int AGRAN = 128 * (BK / 8);               // 1024
    constexpr int BGRAN = BK * (TN_ / 8);

    const int tid  = threadIdx.x;
    const int wid  = tid >> 5;
    const int lane = tid & 31;
    const int m0 = blockIdx.y * 128;
    const int n0 = blockIdx.x * TN_;

    const int wm = (wid & 1) * 64;
    const int wn = (wid >> 1) * 32;

    const uint32_t sb = smem_u32(dsm);

    float acc[4][4][4];
    #pragma unroll
    for (int i = 0; i < 4; i++)
        #pragma unroll
        for (int j = 0; j < 4; j++)
            #pragma unroll
            for (int k = 0; k < 4; k++) acc[i][j][k] = 0.0f;

    const int nk = K / BK;

    auto issue = [&](int slot, int kc) {
        const uint32_t s = sb + (uint32_t)slot * STG;
        for (int i = tid; i < AGRAN; i += NT) {        // A: 128 rows x 8 granules
            int r = i >> 3, c = i & 7;
            uint32_t off = (uint32_t)(r * (SKA_H * 2) + c * 16);
            size_t g = (size_t)(m0 + r) * K + (size_t)kc * BK + c * 8;
            cp16(s + off, A + g);
        }
        for (int i = tid; i < BGRAN; i += NT) {        // B: 64 rows x TN_/8 granules
            int r = i / (TN_ / 8), c = i % (TN_ / 8);
            uint32_t off = (uint32_t)(r * (SKB_ * 2) + c * 16);
            size_t g = (size_t)(kc * BK + r) * N + n0 + c * 8;
            cp16(s + OFF_B + off, B + g);
        }
    };

    // prologue: 2 stages in flight
    issue(0, 0);
    asm volatile("cp.async.commit_group;");
    if (nk > 1) issue(1, 1);
    asm volatile("cp.async.commit_group;");

    const int lm_row = lane & 15;
    const int lm_kch = (lane >> 4) * 8;

    for (int kt = 0; kt < nk; kt++) {
        asm volatile("cp.async.wait_group 1;");   // tile kt arrived
        __syncthreads();                          // + all reads of slot (kt-1)%3 done

        // issue tile kt+2 into slot (kt+2)%3 == (kt-1)%3 (now safe)
        if (kt + 2 < nk) {
            int ps = kt + 2; ps -= (ps / 3) * 3;
            issue(ps, kt + 2);
        }
        asm volatile("cp.async.commit_group;");

        const uint32_t stg = sb + (uint32_t)(kt % 3) * STG;

        #pragma unroll
        for (int ks = 0; ks < BK / 16; ks++) {
            const int k0 = ks * 16;
            uint32_t ah[4][4], bb[2][4];
            #pragma unroll
            for (int mi = 0; mi < 4; mi++) {
                uint32_t off = (uint32_t)((wm + mi * 16 + lm_row) * (SKA_H * 2)
                                          + (k0 + lm_kch) * 2);
                ldsm_x4(ah[mi], stg + off);
            }
            #pragma unroll
            for (int np = 0; np < 2; np++) {
                uint32_t off = (uint32_t)((k0 + lm_row) * (SKB_ * 2)
                                          + (wn + np * 16 + lm_kch) * 2);
                ldsm_x4_t(bb[np], stg + OFF_B + off);
            }
            #pragma unroll
            for (int mi = 0; mi < 4; mi++) {
                #pragma unroll
                for (int nj = 0; nj < 4; nj++) {
                    const uint32_t* bp = &bb[nj >> 1][(nj & 1) * 2];
                    mma_fp16(acc[mi][nj], ah[mi], bp);
                }
            }
        }
        // no trailing barrier: next iteration's sync protects slot reuse
    }

    const int er = lane >> 2;
    const int ec = (lane & 3) * 2;
    #pragma unroll
    for (int mi = 0; mi < 4; mi++) {
        #pragma unroll
        for (int nj = 0; nj < 4; nj++) {
            const int row = m0 + wm + mi * 16 + er;
            const int col = n0 + wn + nj * 8 + ec;
            float2 v01; v01.x = acc[mi][nj][0]; v01.y = acc[mi][nj][1];
            float2 v23; v23.x = acc[mi][nj][2]; v23.y = acc[mi][nj][3];
            *(float2*)&C[(size_t)row * N + col]       = v01;
            *(float2*)&C[(size_t)(row + 8) * N + col] = v23;
        }
    }
}

#define SMEM_T64 (3 * (18432 + 64 * 72 * 2))    // 3*27648 = 82944
#define SMEM_T96 (3 * (18432 + 64 * 104 * 2))   // 3*31744 = 95232

// ---------------------------------------------------------------------------
// RoPE in-place on qkv (q: 64 heads, k: 8 heads).
// ---------------------------------------------------------------------------
__global__ void rope_kernel(float* __restrict__ qkv, int n)
{
    int idx = blockIdx.x * blockDim.x + threadIdx.x;
    int total = n * (NHEADS + NKV) * (DHEAD / 2);
    if (idx >= total) return;

    int j   = idx & 31;
    int h   = (idx >> 5) % (NHEADS + NKV);
    int tok = idx / ((NHEADS + NKV) * 32);

    float* base;
    if (h < NHEADS)
        base = qkv + (size_t)tok * QKVW + h * DHEAD;
    else
        base = qkv + (size_t)tok * QKVW + NHEADS * DHEAD + (h - NHEADS) * DHEAD;

    float pos = (float)g_positions[tok];
    float inv_freq = powf(150000.0f, -((float)j) / 32.0f);
    float ang = pos * inv_freq;
    float s, c;
    sincosf(ang, &s, &c);

    float x1 = base[j];
    float x2 = base[j + 32];
    base[j]      = x1 * c - x2 * s;
    base[j + 32] = x2 * c + x1 * s;
}

// ---------------------------------------------------------------------------
// Sliding-window attention with sinks, 4 tokens per block.
// Grid: (n/4, NKV). Block: 256 threads, dynamic smem (~61 KB).
// Union window = 131 slots. Output written as single fp16.
// ---------------------------------------------------------------------------
#define UNI 131
#define ATTN_SMEM ((8976 + 2048 + 4224 + 32) * 4)   // 61120 B

__global__ __launch_bounds__(256) void attn_kernel(
    const float* __restrict__ qkv, const float* __restrict__ sinks,
    __half* __restrict__ out16, int n)
{
    float* kbuf = (float*)dsm;            // [132][68] (K, then V)
    float* qs   = kbuf + 8976;            // [4][8][64] scaled q
    float* sc   = qs + 2048;              // [4][8][132] scores -> probs
    float* dinv = sc + 4224;              // [32]

    const int tok0 = blockIdx.x * 4;
    const int kv   = blockIdx.y;
    const int tid  = threadIdx.x;
    const int lane = tid & 31;
    const int wid  = tid >> 5;

    const int p0 = g_positions[tok0];

    for (int i = tid; i < 4 * GRP * DHEAD; i += 256) {
        int j = i >> 9, r = i & 511;
        qs[((j << 3) + (r >> 6)) * 64 + (r & 63)] =
            qkv[(size_t)(tok0 + j) * QKVW + (size_t)kv * GRP * DHEAD + r] * 0.125f;
    }

    for (int i = tid; i < UNI * (DHEAD / 4); i += 256) {
        int u  = i >> 4;
        int c4 = (i & 15) << 2;
        int t = p0 - (WIN - 1) + u;
        t = max(0, min(t, n - 1));
        float4 kd = *(const float4*)(qkv + (size_t)t * QKVW + NHEADS * DHEAD
                                     + (size_t)kv * DHEAD + c4);
        *(float4*)&kbuf[u * 68 + c4] = kd;
    }
    __syncthreads();

    if (tid < UNI) {
        const int u = tid;
        float s[4][GRP];
        #pragma unroll
        for (int j = 0; j < 4; j++)
            #pragma unroll
            for (int g = 0; g < GRP; g++) s[j][g] = 0.0f;

        #pragma unroll 4
        for (int d4 = 0; d4 < DHEAD / 4; d4++) {
            float4 kd = *(const float4*)&kbuf[u * 68 + d4 * 4];
            #pragma unroll
            for (int j = 0; j < 4; j++)
                #pragma unroll
                for (int g = 0; g < GRP; g++) {
                    float4 qv = *(const float4*)&qs[((j << 3) + g) * 64 + d4 * 4];
                    s[j][g] += kd.x * qv.x + kd.y * qv.y
                             + kd.z * qv.z + kd.w * qv.w;
                }
        }

        const bool tvalid = (p0 - (WIN - 1) + u) >= 0;
        #pragma unroll
        for (int j = 0; j < 4; j++) {
            int w = u - j;
            bool inw = (w >= 0) && (w < WIN);
            #pragma unroll
            for (int g = 0; g < GRP; g++)
                sc[((j << 3) + g) * 132 + u] =
                    inw ? (tvalid ? s[j][g] : -INFINITY) : 0.0f;
        }
    }
    __syncthreads();

    #pragma unroll
    for (int pp = 0; pp < 4; pp++) {
        int p = (wid << 2) + pp;
        int j = p >> 3, g = p & 7;
        float* base = &sc[p * 132];
        float vals[4];
        #pragma unroll
        for (int i = 0; i < 4; i++)
            vals[i] = base[j + lane + i * 32];
        float m = fmaxf(fmaxf(vals[0], vals[1]), fmaxf(vals[2], vals[3]));
        #pragma unroll
        for (int off = 16; off; off >>= 1)
            m = fmaxf(m, __shfl_xor_sync(0xffffffffu, m, off));
        float snk = sinks[kv * GRP + g];
        m = fmaxf(m, snk);
        float ssum = 0.0f;
        #pragma unroll
        for (int i = 0; i < 4; i++) {
            float pv = expf(vals[i] - m);
            base[j + lane + i * 32] = pv;
            ssum += pv;
        }
        #pragma unroll
        for (int off = 16; off; off >>= 1)
            ssum += __shfl_xor_sync(0xffffffffu, ssum, off);
        if (lane == 0)
            dinv[p] = 1.0f / (ssum + expf(snk - m));
    }

    for (int i = tid; i < UNI * (DHEAD / 4); i += 256) {
        int u  = i >> 4;
        int c4 = (i & 15) << 2;
        int t = p0 - (WIN - 1) + u;
        t = max(0, min(t, n - 1));
        float4 vd = *(const float4*)(qkv + (size_t)t * QKVW
                                     + (NHEADS + NKV) * DHEAD
                                     + (size_t)kv * DHEAD + c4);
        *(float4*)&kbuf[u * 68 + c4] = vd;
    }
    __syncthreads();

    {
        const int g  = wid;
        const int d2 = lane * 2;
        float a[4][2];
        #pragma unroll
        for (int j = 0; j < 4; j++) { a[j][0] = 0.f; a[j][1] = 0.f; }

        #pragma unroll 4
        for (int u = 0; u < UNI; u++) {
            float2 vd = *(const float2*)&kbuf[u * 68 + d2];
            #pragma unroll
            for (int j = 0; j < 4; j++) {
                float pv = sc[((j << 3) + g) * 132 + u];
                a[j][0] += pv * vd.x;
                a[j][1] += pv * vd.y;
            }
        }

        #pragma unroll
        for (int j = 0; j < 4; j++) {
            float di = dinv[(j << 3) + g];
            size_t o = (size_t)(tok0 + j) * AOW
                     + ((size_t)kv * GRP + g) * DHEAD + d2;
            __half2 hv = __halves2half2(__float2half(a[j][0] * di),
                                        __float2half(a[j][1] * di));
            *(__half2*)&out16[o] = hv;
        }
    }
}

// ---------------------------------------------------------------------------
extern "C" void kernel_launch(void* const* d_in, const int* in_sizes, int n_in,
                              void* d_out, int out_size)
{
    const float* hs    = (const float*)d_in[0];
    const float* wqkv  = (const float*)d_in[1];
    const float* wo    = (const float*)d_in[2];
    const float* sinks = (const float*)d_in[3];
    const void*  pos   = (const void*)d_in[4];
    float*       out   = (float*)d_out;

    const int n = in_sizes[0] / HDIM;   // 1024

    float* qkv_ptr;
    __half *ah, *ath, *wq, *wo16;
    cudaGetSymbolAddress((void**)&qkv_ptr, g_qkv);
    cudaGetSymbolAddress((void**)&ah,   g_ah);
    cudaGetSymbolAddress((void**)&ath,  g_ath);
    cudaGetSymbolAddress((void**)&wq,   g_wq);
    cudaGetSymbolAddress((void**)&wo16, g_wo);

    cudaFuncSetAttribute(gemm1p_kernel<64>,
                         cudaFuncAttributeMaxDynamicSharedMemorySize, SMEM_T64);
    cudaFuncSetAttribute(gemm1p_kernel<96>,
                         cudaFuncAttributeMaxDynamicSharedMemorySize, SMEM_T96);
    cudaFuncSetAttribute(attn_kernel,
                         cudaFuncAttributeMaxDynamicSharedMemorySize, ATTN_SMEM);

    // 0) normalize positions
    norm_pos_kernel<<<1, 1024>>>(pos, n);

    // 1) fused fp16 conversions: hs, Wqkv, Wo (one launch)
    {
        int n4_hs = (n * HDIM) / 4;
        int n4_wq = (HDIM * QKVW) / 4;
        int n4_wo = (AOW * HDIM) / 4;
        int tot = n4_hs + n4_wq + n4_wo;
        cvt_all_kernel<<<(tot + 255) / 256, 256>>>(hs, wqkv, wo, ah, wq, wo16,
                                                   n4_hs, n4_wq, n4_wo);
    }

    // 2) qkv = hs @ Wqkv   (fp16 1-pass, BK=64, N tile 64: 5120 = 80*64)
    {
        dim3 grid(QKVW / 64, n / 128);
        gemm1p_kernel<64><<<grid, 128, SMEM_T64>>>(ah, wq, qkv_ptr,
                                                   n, QKVW, HDIM);
    }

    // 3) RoPE in place on q and k
    {
        int total = n * (NHEADS + NKV) * (DHEAD / 2);
        rope_kernel<<<(total + 255) / 256, 256>>>(qkv_ptr, n);
    }

    // 4) attention (4 tokens/block), writes fp16 directly
    {
        dim3 grid(n / 4, NKV);
        attn_kernel<<<grid, 256, ATTN_SMEM>>>(qkv_ptr, sinks, ath, n);
    }

    // 5) out = attn @ Wo   (fp16 1-pass, BK=64, N tile 96: 2880 = 30*96)
    {
        dim3 grid(HDIM / 96, n / 128);
        gemm1p_kernel<96><<<grid, 192, SMEM_T96>>>(ath, wo16, out,
                                                   n, HDIM, AOW);
    }
}